// round 2
// baseline (speedup 1.0000x reference)
#include <cuda_runtime.h>
#include <math.h>

#define C_DIM 128
#define NMAX  50000
#define EMAX  800000

// ---------------- scratch (device globals: sanctioned workaround, no allocs) ---
__device__ float g_h[(size_t)NMAX * C_DIM];     // h = x @ W
__device__ float g_agg[(size_t)NMAX * C_DIM];   // aggregation / post-BN x / conv2 out
__device__ float g_ss[NMAX];                    // per-node src score
__device__ float g_sd[NMAX];                    // per-node dst score
__device__ int   g_rowptr[NMAX + 1];
__device__ int   g_cursor[NMAX];                // degree -> cursor
__device__ int   g_csrc[EMAX];                  // CSR: src node per (dst-sorted) edge

// ---------------- CSR build --------------------------------------------------
__global__ void k_hist(const int* __restrict__ dst, int E, int* __restrict__ deg) {
    int i = blockIdx.x * blockDim.x + threadIdx.x;
    if (i < E) atomicAdd(&deg[dst[i]], 1);
}

__global__ void k_scan(int* __restrict__ deg_cursor, int* __restrict__ rowptr, int N, int E) {
    __shared__ int part[1024];
    int tid = threadIdx.x;
    int chunk = (N + 1023) >> 10;
    int beg = tid * chunk;
    int end = min(beg + chunk, N);
    int s = 0;
    for (int i = beg; i < end; i++) s += deg_cursor[i];
    part[tid] = s;
    __syncthreads();
    for (int off = 1; off < 1024; off <<= 1) {
        int v = (tid >= off) ? part[tid - off] : 0;
        __syncthreads();
        part[tid] += v;
        __syncthreads();
    }
    int run = (tid > 0) ? part[tid - 1] : 0;
    for (int i = beg; i < end; i++) {
        int d = deg_cursor[i];
        rowptr[i] = run;
        deg_cursor[i] = run;   // becomes scatter cursor
        run += d;
    }
    if (tid == 0) rowptr[N] = E;
}

__global__ void k_scatter(const int* __restrict__ src, const int* __restrict__ dst,
                          int E, int* __restrict__ cursor, int* __restrict__ csrc) {
    int i = blockIdx.x * blockDim.x + threadIdx.x;
    if (i < E) {
        int p = atomicAdd(&cursor[dst[i]], 1);
        csrc[p] = src[i];
    }
}

// ---------------- GEMM: H[M,128] = X[M,128] @ W[128,128] ---------------------
// block tile: 64 rows x 128 cols, 256 threads, 4x8 micro-tile, W+Xtile in smem
#define GPX 132
__global__ void k_gemm(const float* __restrict__ X, const float* __restrict__ W,
                       float* __restrict__ H, int M) {
    extern __shared__ float sm[];
    float* Ws = sm;               // 128*128
    float* Xs = sm + 128 * 128;   // 64 * GPX
    int tid = threadIdx.x;

    for (int i = tid; i < 128 * 32; i += 256)
        ((float4*)Ws)[i] = ((const float4*)W)[i];

    int m0 = blockIdx.x * 64;
    int rows = min(64, M - m0);
    for (int i = tid; i < 64 * 32; i += 256) {
        int r = i >> 5, c = i & 31;
        float4 v = (r < rows) ? ((const float4*)(X + (size_t)(m0 + r) * 128))[c]
                              : make_float4(0.f, 0.f, 0.f, 0.f);
        *(float4*)(Xs + r * GPX + c * 4) = v;
    }
    __syncthreads();

    int cy = tid >> 4, cx = tid & 15;   // rows cy*4.., cols cx*8..
    float acc[4][8];
#pragma unroll
    for (int i = 0; i < 4; i++)
#pragma unroll
        for (int j = 0; j < 8; j++) acc[i][j] = 0.f;

#pragma unroll 4
    for (int k = 0; k < 128; k++) {
        float av[4];
#pragma unroll
        for (int i = 0; i < 4; i++) av[i] = Xs[(cy * 4 + i) * GPX + k];
        float4 b0 = *(const float4*)(Ws + k * 128 + cx * 8);
        float4 b1 = *(const float4*)(Ws + k * 128 + cx * 8 + 4);
        float bv[8] = {b0.x, b0.y, b0.z, b0.w, b1.x, b1.y, b1.z, b1.w};
#pragma unroll
        for (int i = 0; i < 4; i++)
#pragma unroll
            for (int j = 0; j < 8; j++) acc[i][j] = fmaf(av[i], bv[j], acc[i][j]);
    }

#pragma unroll
    for (int i = 0; i < 4; i++) {
        int r = cy * 4 + i;
        if (r < rows) {
            float* dst = H + (size_t)(m0 + r) * 128 + cx * 8;
            *(float4*)dst       = make_float4(acc[i][0], acc[i][1], acc[i][2], acc[i][3]);
            *(float4*)(dst + 4) = make_float4(acc[i][4], acc[i][5], acc[i][6], acc[i][7]);
        }
    }
}

// ---------------- per-node attention scores ----------------------------------
__global__ void k_scores(const float* __restrict__ h, const float* __restrict__ asrc,
                         const float* __restrict__ adst, float* __restrict__ ss,
                         float* __restrict__ sd, int N) {
    int gt = blockIdx.x * blockDim.x + threadIdx.x;
    int w = gt >> 5, lane = gt & 31;
    if (w >= N) return;
    float4 hv = *(const float4*)(h + (size_t)w * 128 + lane * 4);
    float4 a1 = ((const float4*)asrc)[lane];
    float4 a2 = ((const float4*)adst)[lane];
    float d1 = hv.x * a1.x + hv.y * a1.y + hv.z * a1.z + hv.w * a1.w;
    float d2 = hv.x * a2.x + hv.y * a2.y + hv.z * a2.z + hv.w * a2.w;
#pragma unroll
    for (int o = 16; o; o >>= 1) {
        d1 += __shfl_xor_sync(0xffffffffu, d1, o);
        d2 += __shfl_xor_sync(0xffffffffu, d2, o);
    }
    if (lane == 0) { ss[w] = d1; sd[w] = d2; }
}

// ---------------- warp-per-dst softmax-weighted aggregation (no atomics) -----
__global__ void k_agg(const float* __restrict__ h, const float* __restrict__ ss,
                      const float* __restrict__ sdv, const int* __restrict__ rowptr,
                      const int* __restrict__ csrc, float* __restrict__ out, int N) {
    int gt = blockIdx.x * blockDim.x + threadIdx.x;
    int w = gt >> 5, lane = gt & 31;
    if (w >= N) return;
    int beg = rowptr[w], end = rowptr[w + 1];
    float sd = sdv[w];

    // pass 1: max score
    float mx = -1e30f;
    for (int k = beg + lane; k < end; k += 32) {
        float e = ss[csrc[k]] + sd;
        e = (e > 0.f) ? e : 0.2f * e;
        mx = fmaxf(mx, e);
    }
#pragma unroll
    for (int o = 16; o; o >>= 1) mx = fmaxf(mx, __shfl_xor_sync(0xffffffffu, mx, o));

    // pass 2: fused exp-weighted sum + denominator
    float4 acc = make_float4(0.f, 0.f, 0.f, 0.f);
    float den = 0.f;
    for (int k = beg; k < end; k++) {
        int s = csrc[k];                   // warp-uniform broadcast load
        float e = ss[s] + sd;
        e = (e > 0.f) ? e : 0.2f * e;
        float wgt = __expf(e - mx);
        den += wgt;
        float4 hv = *(const float4*)(h + (size_t)s * 128 + lane * 4);
        acc.x = fmaf(wgt, hv.x, acc.x);
        acc.y = fmaf(wgt, hv.y, acc.y);
        acc.z = fmaf(wgt, hv.z, acc.z);
        acc.w = fmaf(wgt, hv.w, acc.w);
    }
    float inv = 1.f / (den + 1e-16f);
    *(float4*)(out + (size_t)w * 128 + lane * 4) =
        make_float4(acc.x * inv, acc.y * inv, acc.z * inv, acc.w * inv);
}

// ---------------- bias + BN(eval) + ReLU, in-place ---------------------------
__global__ void k_bnrelu(float* __restrict__ x, const float* __restrict__ b,
                         const float* __restrict__ gamma, const float* __restrict__ beta,
                         const float* __restrict__ rmean, const float* __restrict__ rvar,
                         int N) {
    int idx = blockIdx.x * blockDim.x + threadIdx.x;   // one float4 each
    if (idx >= N * 32) return;
    int c4 = idx & 31;
    float4 xv = ((float4*)x)[idx];
    float4 bb = ((const float4*)b)[c4];
    float4 gg = ((const float4*)gamma)[c4];
    float4 bt = ((const float4*)beta)[c4];
    float4 mm = ((const float4*)rmean)[c4];
    float4 vv = ((const float4*)rvar)[c4];
    float4 o;
    o.x = fmaxf((xv.x + bb.x - mm.x) * rsqrtf(vv.x + 1e-5f) * gg.x + bt.x, 0.f);
    o.y = fmaxf((xv.y + bb.y - mm.y) * rsqrtf(vv.y + 1e-5f) * gg.y + bt.y, 0.f);
    o.z = fmaxf((xv.z + bb.z - mm.z) * rsqrtf(vv.z + 1e-5f) * gg.z + bt.z, 0.f);
    o.w = fmaxf((xv.w + bb.w - mm.w) * rsqrtf(vv.w + 1e-5f) * gg.w + bt.w, 0.f);
    ((float4*)x)[idx] = o;
}

// ---------------- fused link predictor ---------------------------------------
// per 64-query tile: gather (x2[e0]+b2)*(x2[e1]+b2) -> smem, GEMM vs Wp1 (smem),
// ReLU, dot with Wp2, sigmoid. 256 threads, 4x8 micro-tile.
__global__ void k_pred(const float* __restrict__ x, const float* __restrict__ b2,
                       const float* __restrict__ Wp1, const float* __restrict__ bp1,
                       const float* __restrict__ Wp2, const float* __restrict__ bp2,
                       const int* __restrict__ edges, int Q, float* __restrict__ out) {
    extern __shared__ float sm[];
    float* Ws   = sm;                    // 128*128
    float* Hs   = sm + 128 * 128;        // 64*GPX
    float* bp1s = Hs + 64 * GPX;         // 128
    float* wp2s = bp1s + 128;            // 128
    float* b2s  = wp2s + 128;            // 128
    int tid = threadIdx.x;

    for (int i = tid; i < 128 * 32; i += 256)
        ((float4*)Ws)[i] = ((const float4*)Wp1)[i];
    if (tid < 128) { bp1s[tid] = bp1[tid]; wp2s[tid] = Wp2[tid]; b2s[tid] = b2[tid]; }
    __syncthreads();

    int q0 = blockIdx.x * 64;
    for (int i = tid; i < 64 * 32; i += 256) {
        int r = i >> 5, c4 = i & 31;
        int q = q0 + r;
        float4 v = make_float4(0.f, 0.f, 0.f, 0.f);
        if (q < Q) {
            int e0 = edges[q], e1 = edges[Q + q];
            float4 xa = *(const float4*)(x + (size_t)e0 * 128 + c4 * 4);
            float4 xb = *(const float4*)(x + (size_t)e1 * 128 + c4 * 4);
            float4 bb = *(const float4*)(b2s + c4 * 4);
            v.x = (xa.x + bb.x) * (xb.x + bb.x);
            v.y = (xa.y + bb.y) * (xb.y + bb.y);
            v.z = (xa.z + bb.z) * (xb.z + bb.z);
            v.w = (xa.w + bb.w) * (xb.w + bb.w);
        }
        *(float4*)(Hs + r * GPX + c4 * 4) = v;
    }
    __syncthreads();

    int cy = tid >> 4, cx = tid & 15;
    float acc[4][8];
#pragma unroll
    for (int i = 0; i < 4; i++)
#pragma unroll
        for (int j = 0; j < 8; j++) acc[i][j] = 0.f;

#pragma unroll 4
    for (int k = 0; k < 128; k++) {
        float av[4];
#pragma unroll
        for (int i = 0; i < 4; i++) av[i] = Hs[(cy * 4 + i) * GPX + k];
        float4 b0 = *(const float4*)(Ws + k * 128 + cx * 8);
        float4 b1 = *(const float4*)(Ws + k * 128 + cx * 8 + 4);
        float bv[8] = {b0.x, b0.y, b0.z, b0.w, b1.x, b1.y, b1.z, b1.w};
#pragma unroll
        for (int i = 0; i < 4; i++)
#pragma unroll
            for (int j = 0; j < 8; j++) acc[i][j] = fmaf(av[i], bv[j], acc[i][j]);
    }

    float bp2v = bp2[0];
#pragma unroll
    for (int i = 0; i < 4; i++) {
        float sum = 0.f;
#pragma unroll
        for (int j = 0; j < 8; j++) {
            int c = cx * 8 + j;
            float v = fmaxf(acc[i][j] + bp1s[c], 0.f);
            sum = fmaf(v, wp2s[c], sum);
        }
        sum += __shfl_xor_sync(0xffffffffu, sum, 8);
        sum += __shfl_xor_sync(0xffffffffu, sum, 4);
        sum += __shfl_xor_sync(0xffffffffu, sum, 2);
        sum += __shfl_xor_sync(0xffffffffu, sum, 1);
        if (cx == 0) {
            int q = q0 + cy * 4 + i;
            if (q < Q) out[q] = 1.f / (1.f + __expf(-(sum + bp2v)));
        }
    }
}

// ---------------- launch ------------------------------------------------------
extern "C" void kernel_launch(void* const* d_in, const int* in_sizes, int n_in,
                              void* d_out, int out_size) {
    const float* emb    = (const float*)d_in[0];
    const float* W1     = (const float*)d_in[1];
    const float* a_src1 = (const float*)d_in[2];
    const float* a_dst1 = (const float*)d_in[3];
    const float* b1     = (const float*)d_in[4];
    const float* gamma  = (const float*)d_in[5];
    const float* beta   = (const float*)d_in[6];
    const float* rmean  = (const float*)d_in[7];
    const float* rvar   = (const float*)d_in[8];
    const float* W2     = (const float*)d_in[9];
    const float* a_src2 = (const float*)d_in[10];
    const float* a_dst2 = (const float*)d_in[11];
    const float* b2     = (const float*)d_in[12];
    const float* Wp1    = (const float*)d_in[13];
    const float* bp1    = (const float*)d_in[14];
    const float* Wp2    = (const float*)d_in[15];
    const float* bp2    = (const float*)d_in[16];
    const int*   eidx   = (const int*)d_in[17];
    const int*   edges  = (const int*)d_in[18];

    int N = in_sizes[0] / C_DIM;
    int E = in_sizes[17] / 2;
    int Q = in_sizes[18] / 2;

    float *h, *agg, *ss, *sd;
    int *rowptr, *cursor, *csrc;
    cudaGetSymbolAddress((void**)&h, g_h);
    cudaGetSymbolAddress((void**)&agg, g_agg);
    cudaGetSymbolAddress((void**)&ss, g_ss);
    cudaGetSymbolAddress((void**)&sd, g_sd);
    cudaGetSymbolAddress((void**)&rowptr, g_rowptr);
    cudaGetSymbolAddress((void**)&cursor, g_cursor);
    cudaGetSymbolAddress((void**)&csrc, g_csrc);

    const size_t smg = (128 * 128 + 64 * GPX) * sizeof(float);
    const size_t smp = (128 * 128 + 64 * GPX + 3 * 128) * sizeof(float);
    cudaFuncSetAttribute(k_gemm, cudaFuncAttributeMaxDynamicSharedMemorySize, (int)smg);
    cudaFuncSetAttribute(k_pred, cudaFuncAttributeMaxDynamicSharedMemorySize, (int)smp);

    const int TB = 256;
    const int nw_blocks = (N * 32 + TB - 1) / TB;   // warp-per-node kernels

    // CSR by destination (shared by both convs)
    cudaMemsetAsync(cursor, 0, N * sizeof(int));
    k_hist<<<(E + TB - 1) / TB, TB>>>(eidx + E, E, cursor);
    k_scan<<<1, 1024>>>(cursor, rowptr, N, E);
    k_scatter<<<(E + TB - 1) / TB, TB>>>(eidx, eidx + E, E, cursor, csrc);

    // conv1
    k_gemm<<<(N + 63) / 64, 256, smg>>>(emb, W1, h, N);
    k_scores<<<nw_blocks, TB>>>(h, a_src1, a_dst1, ss, sd, N);
    k_agg<<<nw_blocks, TB>>>(h, ss, sd, rowptr, csrc, agg, N);
    k_bnrelu<<<nw_blocks, TB>>>(agg, b1, gamma, beta, rmean, rvar, N);

    // conv2
    k_gemm<<<(N + 63) / 64, 256, smg>>>(agg, W2, h, N);
    k_scores<<<nw_blocks, TB>>>(h, a_src2, a_dst2, ss, sd, N);
    k_agg<<<nw_blocks, TB>>>(h, ss, sd, rowptr, csrc, agg, N);

    // link predictor (b2 folded into gather)
    k_pred<<<(Q + 63) / 64, 256, smp>>>(agg, b2, Wp1, bp1, Wp2, bp2, edges, Q,
                                        (float*)d_out);
}

// round 3
// speedup vs baseline: 1.4204x; 1.4204x over previous
#include <cuda_runtime.h>
#include <math.h>

#define C_DIM 128
#define NMAX  50000
#define EMAX  800000
#define PAD   132   // smem row pitch (floats): conflict-free for tf32 mma frag patterns

// ---------------- scratch (device globals; no allocs) ------------------------
__device__ float g_h[(size_t)NMAX * C_DIM];
__device__ float g_agg[(size_t)NMAX * C_DIM];
__device__ float g_ss[NMAX];
__device__ float g_sd[NMAX];
__device__ int   g_rowptr[NMAX + 1];
__device__ int   g_cursor[NMAX];
__device__ int   g_csrc[EMAX];

// ---------------- helpers -----------------------------------------------------
__device__ __forceinline__ unsigned f2tf(float x) {
    unsigned r;
    asm("cvt.rna.tf32.f32 %0, %1;" : "=r"(r) : "f"(x));
    return r;
}
__device__ __forceinline__ void mma_tf32(float c[4], const unsigned a[4],
                                         const unsigned b[2]) {
    asm volatile(
        "mma.sync.aligned.m16n8k8.row.col.f32.tf32.tf32.f32 "
        "{%0,%1,%2,%3}, {%4,%5,%6,%7}, {%8,%9}, {%0,%1,%2,%3};"
        : "+f"(c[0]), "+f"(c[1]), "+f"(c[2]), "+f"(c[3])
        : "r"(a[0]), "r"(a[1]), "r"(a[2]), "r"(a[3]), "r"(b[0]), "r"(b[1]));
}
__device__ __forceinline__ uint4 cvt4(float4 v) {
    uint4 o;
    o.x = f2tf(v.x); o.y = f2tf(v.y); o.z = f2tf(v.z); o.w = f2tf(v.w);
    return o;
}

// ---------------- CSR build --------------------------------------------------
__global__ void k_hist(const int* __restrict__ dst, int E, int* __restrict__ deg) {
    int i = blockIdx.x * blockDim.x + threadIdx.x;
    if (i < E) atomicAdd(&deg[dst[i]], 1);
}

__global__ void k_scan(int* __restrict__ deg_cursor, int* __restrict__ rowptr, int N, int E) {
    __shared__ int part[1024];
    int tid = threadIdx.x;
    int chunk = (N + 1023) >> 10;
    int beg = tid * chunk;
    int end = min(beg + chunk, N);
    int s = 0;
    for (int i = beg; i < end; i++) s += deg_cursor[i];
    part[tid] = s;
    __syncthreads();
    for (int off = 1; off < 1024; off <<= 1) {
        int v = (tid >= off) ? part[tid - off] : 0;
        __syncthreads();
        part[tid] += v;
        __syncthreads();
    }
    int run = (tid > 0) ? part[tid - 1] : 0;
    for (int i = beg; i < end; i++) {
        int d = deg_cursor[i];
        rowptr[i] = run;
        deg_cursor[i] = run;
        run += d;
    }
    if (tid == 0) rowptr[N] = E;
}

__global__ void k_scatter(const int* __restrict__ src, const int* __restrict__ dst,
                          int E, int* __restrict__ cursor, int* __restrict__ csrc) {
    int i = blockIdx.x * blockDim.x + threadIdx.x;
    if (i < E) {
        int p = atomicAdd(&cursor[dst[i]], 1);
        csrc[p] = src[i];
    }
}

// ---------------- tensor-core GEMM: H[M,128] = X[M,128] @ W[128,128] ---------
// block: 128 rows x 128 cols, 256 threads = 8 warps, warp tile 32x64,
// mma.m16n8k8.tf32, K=128 smem-resident, pitch PAD=132 (conflict-free).
__global__ void __launch_bounds__(256) k_gemm_tc(
    const float* __restrict__ X, const float* __restrict__ W,
    float* __restrict__ H, int M) {
    extern __shared__ unsigned smu[];
    unsigned* Ws = smu;               // [128 k][PAD]
    unsigned* Xs = smu + 128 * PAD;   // [128 r][PAD]
    int tid = threadIdx.x;
    int m0 = blockIdx.x * 128;
    int rows = min(128, M - m0);

    for (int i = tid; i < 128 * 32; i += 256) {
        int k = i >> 5, n4 = i & 31;
        *(uint4*)(Ws + k * PAD + n4 * 4) = cvt4(((const float4*)W)[i]);
    }
    for (int i = tid; i < 128 * 32; i += 256) {
        int r = i >> 5, c4 = i & 31;
        float4 v = (r < rows) ? ((const float4*)(X + (size_t)(m0 + r) * 128))[c4]
                              : make_float4(0.f, 0.f, 0.f, 0.f);
        *(uint4*)(Xs + r * PAD + c4 * 4) = cvt4(v);
    }
    __syncthreads();

    int wid = tid >> 5, lane = tid & 31;
    int rg = wid & 3, cg = wid >> 2;           // 4 row-groups x 2 col-groups
    int r0 = rg * 32, n0 = cg * 64;
    int gid = lane >> 2, tig = lane & 3;

    float acc[2][8][4];
#pragma unroll
    for (int mi = 0; mi < 2; mi++)
#pragma unroll
        for (int ni = 0; ni < 8; ni++)
#pragma unroll
            for (int j = 0; j < 4; j++) acc[mi][ni][j] = 0.f;

#pragma unroll 4
    for (int kk = 0; kk < 16; kk++) {
        int k0 = kk * 8;
        unsigned a[2][4], b[8][2];
#pragma unroll
        for (int mi = 0; mi < 2; mi++) {
            const unsigned* base = Xs + (r0 + mi * 16 + gid) * PAD + k0 + tig;
            a[mi][0] = base[0];
            a[mi][1] = base[8 * PAD];
            a[mi][2] = base[4];
            a[mi][3] = base[8 * PAD + 4];
        }
#pragma unroll
        for (int ni = 0; ni < 8; ni++) {
            const unsigned* base = Ws + (k0 + tig) * PAD + n0 + ni * 8 + gid;
            b[ni][0] = base[0];
            b[ni][1] = base[4 * PAD];
        }
#pragma unroll
        for (int mi = 0; mi < 2; mi++)
#pragma unroll
            for (int ni = 0; ni < 8; ni++) mma_tf32(acc[mi][ni], a[mi], b[ni]);
    }

#pragma unroll
    for (int mi = 0; mi < 2; mi++) {
        int rlo = r0 + mi * 16 + gid;
#pragma unroll
        for (int ni = 0; ni < 8; ni++) {
            int col = n0 + ni * 8 + tig * 2;
            if (rlo < rows)
                *(float2*)(H + (size_t)(m0 + rlo) * 128 + col) =
                    make_float2(acc[mi][ni][0], acc[mi][ni][1]);
            if (rlo + 8 < rows)
                *(float2*)(H + (size_t)(m0 + rlo + 8) * 128 + col) =
                    make_float2(acc[mi][ni][2], acc[mi][ni][3]);
        }
    }
}

// ---------------- per-node attention scores ----------------------------------
__global__ void k_scores(const float* __restrict__ h, const float* __restrict__ asrc,
                         const float* __restrict__ adst, float* __restrict__ ss,
                         float* __restrict__ sd, int N) {
    int gt = blockIdx.x * blockDim.x + threadIdx.x;
    int w = gt >> 5, lane = gt & 31;
    if (w >= N) return;
    float4 hv = *(const float4*)(h + (size_t)w * 128 + lane * 4);
    float4 a1 = ((const float4*)asrc)[lane];
    float4 a2 = ((const float4*)adst)[lane];
    float d1 = hv.x * a1.x + hv.y * a1.y + hv.z * a1.z + hv.w * a1.w;
    float d2 = hv.x * a2.x + hv.y * a2.y + hv.z * a2.z + hv.w * a2.w;
#pragma unroll
    for (int o = 16; o; o >>= 1) {
        d1 += __shfl_xor_sync(0xffffffffu, d1, o);
        d2 += __shfl_xor_sync(0xffffffffu, d2, o);
    }
    if (lane == 0) { ss[w] = d1; sd[w] = d2; }
}

// ---------------- warp-per-dst softmax-weighted aggregation ------------------
__global__ void k_agg(const float* __restrict__ h, const float* __restrict__ ss,
                      const float* __restrict__ sdv, const int* __restrict__ rowptr,
                      const int* __restrict__ csrc, float* __restrict__ out, int N) {
    int gt = blockIdx.x * blockDim.x + threadIdx.x;
    int w = gt >> 5, lane = gt & 31;
    if (w >= N) return;
    int beg = rowptr[w], end = rowptr[w + 1];
    float sd = sdv[w];

    float mx = -1e30f;
    for (int k = beg + lane; k < end; k += 32) {
        float e = ss[csrc[k]] + sd;
        e = (e > 0.f) ? e : 0.2f * e;
        mx = fmaxf(mx, e);
    }
#pragma unroll
    for (int o = 16; o; o >>= 1) mx = fmaxf(mx, __shfl_xor_sync(0xffffffffu, mx, o));

    float4 acc = make_float4(0.f, 0.f, 0.f, 0.f);
    float den = 0.f;
    for (int k = beg; k < end; k++) {
        int s = csrc[k];
        float e = ss[s] + sd;
        e = (e > 0.f) ? e : 0.2f * e;
        float wgt = __expf(e - mx);
        den += wgt;
        float4 hv = *(const float4*)(h + (size_t)s * 128 + lane * 4);
        acc.x = fmaf(wgt, hv.x, acc.x);
        acc.y = fmaf(wgt, hv.y, acc.y);
        acc.z = fmaf(wgt, hv.z, acc.z);
        acc.w = fmaf(wgt, hv.w, acc.w);
    }
    float inv = 1.f / (den + 1e-16f);
    *(float4*)(out + (size_t)w * 128 + lane * 4) =
        make_float4(acc.x * inv, acc.y * inv, acc.z * inv, acc.w * inv);
}

// ---------------- bias + BN(eval) + ReLU, in-place ---------------------------
__global__ void k_bnrelu(float* __restrict__ x, const float* __restrict__ b,
                         const float* __restrict__ gamma, const float* __restrict__ beta,
                         const float* __restrict__ rmean, const float* __restrict__ rvar,
                         int N) {
    int idx = blockIdx.x * blockDim.x + threadIdx.x;
    if (idx >= N * 32) return;
    int c4 = idx & 31;
    float4 xv = ((float4*)x)[idx];
    float4 bb = ((const float4*)b)[c4];
    float4 gg = ((const float4*)gamma)[c4];
    float4 bt = ((const float4*)beta)[c4];
    float4 mm = ((const float4*)rmean)[c4];
    float4 vv = ((const float4*)rvar)[c4];
    float4 o;
    o.x = fmaxf((xv.x + bb.x - mm.x) * rsqrtf(vv.x + 1e-5f) * gg.x + bt.x, 0.f);
    o.y = fmaxf((xv.y + bb.y - mm.y) * rsqrtf(vv.y + 1e-5f) * gg.y + bt.y, 0.f);
    o.z = fmaxf((xv.z + bb.z - mm.z) * rsqrtf(vv.z + 1e-5f) * gg.z + bt.z, 0.f);
    o.w = fmaxf((xv.w + bb.w - mm.w) * rsqrtf(vv.w + 1e-5f) * gg.w + bt.w, 0.f);
    ((float4*)x)[idx] = o;
}

// ---------------- fused link predictor (tensor core) -------------------------
// per 128-query tile: gather (x[e0]+b2)*(x[e1]+b2) -> smem tf32, MMA vs Wp1,
// ReLU+bp1, dot Wp2 (smem cross-warp reduction), sigmoid.
__global__ void __launch_bounds__(256) k_pred_tc(
    const float* __restrict__ x, const float* __restrict__ b2,
    const float* __restrict__ Wp1, const float* __restrict__ bp1,
    const float* __restrict__ Wp2, const float* __restrict__ bp2,
    const int* __restrict__ edges, int Q, float* __restrict__ out) {
    extern __shared__ unsigned smu[];
    unsigned* Ws = smu;                       // [128 k][PAD] tf32
    unsigned* Hs = smu + 128 * PAD;           // [128 q][PAD] tf32
    float* bp1s = (float*)(smu + 2 * 128 * PAD);   // 128
    float* wp2s = bp1s + 128;                      // 128
    float* b2s  = wp2s + 128;                      // 128
    float* red  = b2s + 128;                       // [128][8]
    int tid = threadIdx.x;
    int q0 = blockIdx.x * 128;

    for (int i = tid; i < 128 * 32; i += 256) {
        int k = i >> 5, n4 = i & 31;
        *(uint4*)(Ws + k * PAD + n4 * 4) = cvt4(((const float4*)Wp1)[i]);
    }
    if (tid < 128) { bp1s[tid] = bp1[tid]; wp2s[tid] = Wp2[tid]; b2s[tid] = b2[tid]; }
    __syncthreads();   // b2s ready before gather uses it

    for (int i = tid; i < 128 * 32; i += 256) {
        int r = i >> 5, c4 = i & 31;
        int q = q0 + r;
        float4 v = make_float4(0.f, 0.f, 0.f, 0.f);
        if (q < Q) {
            int e0 = edges[q], e1 = edges[Q + q];
            float4 xa = *(const float4*)(x + (size_t)e0 * 128 + c4 * 4);
            float4 xb = *(const float4*)(x + (size_t)e1 * 128 + c4 * 4);
            float4 bb = *(const float4*)(b2s + c4 * 4);
            v.x = (xa.x + bb.x) * (xb.x + bb.x);
            v.y = (xa.y + bb.y) * (xb.y + bb.y);
            v.z = (xa.z + bb.z) * (xb.z + bb.z);
            v.w = (xa.w + bb.w) * (xb.w + bb.w);
        }
        *(uint4*)(Hs + r * PAD + c4 * 4) = cvt4(v);
    }
    __syncthreads();

    int wid = tid >> 5, lane = tid & 31;
    int rg = wid & 3, cg = wid >> 2;
    int r0 = rg * 32, n0 = cg * 64;
    int gid = lane >> 2, tig = lane & 3;

    float acc[2][8][4];
#pragma unroll
    for (int mi = 0; mi < 2; mi++)
#pragma unroll
        for (int ni = 0; ni < 8; ni++)
#pragma unroll
            for (int j = 0; j < 4; j++) acc[mi][ni][j] = 0.f;

#pragma unroll 4
    for (int kk = 0; kk < 16; kk++) {
        int k0 = kk * 8;
        unsigned a[2][4], b[8][2];
#pragma unroll
        for (int mi = 0; mi < 2; mi++) {
            const unsigned* base = Hs + (r0 + mi * 16 + gid) * PAD + k0 + tig;
            a[mi][0] = base[0];
            a[mi][1] = base[8 * PAD];
            a[mi][2] = base[4];
            a[mi][3] = base[8 * PAD + 4];
        }
#pragma unroll
        for (int ni = 0; ni < 8; ni++) {
            const unsigned* base = Ws + (k0 + tig) * PAD + n0 + ni * 8 + gid;
            b[ni][0] = base[0];
            b[ni][1] = base[4 * PAD];
        }
#pragma unroll
        for (int mi = 0; mi < 2; mi++)
#pragma unroll
            for (int ni = 0; ni < 8; ni++) mma_tf32(acc[mi][ni], a[mi], b[ni]);
    }

    // epilogue: relu(acc + bp1) dot wp2, partial per thread, reduce via smem
    int slot = cg * 4 + tig;
#pragma unroll
    for (int mi = 0; mi < 2; mi++) {
        float plo = 0.f, phi = 0.f;
#pragma unroll
        for (int ni = 0; ni < 8; ni++) {
            int col = n0 + ni * 8 + tig * 2;
            float w0 = wp2s[col], w1 = wp2s[col + 1];
            float bb0 = bp1s[col], bb1 = bp1s[col + 1];
            plo += fmaxf(acc[mi][ni][0] + bb0, 0.f) * w0
                 + fmaxf(acc[mi][ni][1] + bb1, 0.f) * w1;
            phi += fmaxf(acc[mi][ni][2] + bb0, 0.f) * w0
                 + fmaxf(acc[mi][ni][3] + bb1, 0.f) * w1;
        }
        int rlo = r0 + mi * 16 + gid;
        red[rlo * 8 + slot] = plo;
        red[(rlo + 8) * 8 + slot] = phi;
    }
    __syncthreads();

    if (tid < 128) {
        float s = 0.f;
#pragma unroll
        for (int j = 0; j < 8; j++) s += red[tid * 8 + j];
        int q = q0 + tid;
        if (q < Q) out[q] = 1.f / (1.f + __expf(-(s + bp2[0])));
    }
}

// ---------------- launch ------------------------------------------------------
extern "C" void kernel_launch(void* const* d_in, const int* in_sizes, int n_in,
                              void* d_out, int out_size) {
    const float* emb    = (const float*)d_in[0];
    const float* W1     = (const float*)d_in[1];
    const float* a_src1 = (const float*)d_in[2];
    const float* a_dst1 = (const float*)d_in[3];
    const float* b1     = (const float*)d_in[4];
    const float* gamma  = (const float*)d_in[5];
    const float* beta   = (const float*)d_in[6];
    const float* rmean  = (const float*)d_in[7];
    const float* rvar   = (const float*)d_in[8];
    const float* W2     = (const float*)d_in[9];
    const float* a_src2 = (const float*)d_in[10];
    const float* a_dst2 = (const float*)d_in[11];
    const float* b2     = (const float*)d_in[12];
    const float* Wp1    = (const float*)d_in[13];
    const float* bp1    = (const float*)d_in[14];
    const float* Wp2    = (const float*)d_in[15];
    const float* bp2    = (const float*)d_in[16];
    const int*   eidx   = (const int*)d_in[17];
    const int*   edges  = (const int*)d_in[18];

    int N = in_sizes[0] / C_DIM;
    int E = in_sizes[17] / 2;
    int Q = in_sizes[18] / 2;

    float *h, *agg, *ss, *sd;
    int *rowptr, *cursor, *csrc;
    cudaGetSymbolAddress((void**)&h, g_h);
    cudaGetSymbolAddress((void**)&agg, g_agg);
    cudaGetSymbolAddress((void**)&ss, g_ss);
    cudaGetSymbolAddress((void**)&sd, g_sd);
    cudaGetSymbolAddress((void**)&rowptr, g_rowptr);
    cudaGetSymbolAddress((void**)&cursor, g_cursor);
    cudaGetSymbolAddress((void**)&csrc, g_csrc);

    const size_t smg = (size_t)2 * 128 * PAD * 4;                       // 135168
    const size_t smp = smg + (size_t)(3 * 128 + 128 * 8) * 4;           // +4608
    cudaFuncSetAttribute(k_gemm_tc, cudaFuncAttributeMaxDynamicSharedMemorySize, (int)smg);
    cudaFuncSetAttribute(k_pred_tc, cudaFuncAttributeMaxDynamicSharedMemorySize, (int)smp);

    const int TB = 256;
    const int nw_blocks = (N * 32 + TB - 1) / TB;

    // CSR by destination (shared by both convs)
    cudaMemsetAsync(cursor, 0, N * sizeof(int));
    k_hist<<<(E + TB - 1) / TB, TB>>>(eidx + E, E, cursor);
    k_scan<<<1, 1024>>>(cursor, rowptr, N, E);
    k_scatter<<<(E + TB - 1) / TB, TB>>>(eidx, eidx + E, E, cursor, csrc);

    // conv1
    k_gemm_tc<<<(N + 127) / 128, 256, smg>>>(emb, W1, h, N);
    k_scores<<<nw_blocks, TB>>>(h, a_src1, a_dst1, ss, sd, N);
    k_agg<<<nw_blocks, TB>>>(h, ss, sd, rowptr, csrc, agg, N);
    k_bnrelu<<<nw_blocks, TB>>>(agg, b1, gamma, beta, rmean, rvar, N);

    // conv2
    k_gemm_tc<<<(N + 127) / 128, 256, smg>>>(agg, W2, h, N);
    k_scores<<<nw_blocks, TB>>>(h, a_src2, a_dst2, ss, sd, N);
    k_agg<<<nw_blocks, TB>>>(h, ss, sd, rowptr, csrc, agg, N);

    // link predictor
    k_pred_tc<<<(Q + 127) / 128, 256, smp>>>(agg, b2, Wp1, bp1, Wp2, bp2, edges, Q,
                                             (float*)d_out);
}

// round 4
// speedup vs baseline: 1.8326x; 1.2902x over previous
#include <cuda_runtime.h>
#include <cuda_bf16.h>
#include <math.h>

#define C_DIM 128
#define NMAX  50000
#define EMAX  800000
#define PITCH 72   // smem row pitch in 4B words for packed bf16 fragments

// ---------------- scratch (device globals; no allocs) ------------------------
__device__ float g_h[(size_t)NMAX * C_DIM];
__device__ float g_agg[(size_t)NMAX * C_DIM];
__device__ float g_ss[NMAX];
__device__ float g_sd[NMAX];
__device__ int   g_rowptr[NMAX + 1];
__device__ int   g_cursor[NMAX];
__device__ int   g_csrc[EMAX];

// ---------------- helpers -----------------------------------------------------
__device__ __forceinline__ unsigned packbf(float a, float b) {
    __nv_bfloat162 h = __floats2bfloat162_rn(a, b);
    return *reinterpret_cast<unsigned*>(&h);
}
__device__ __forceinline__ void mma_bf16(float c[4], const unsigned a[4],
                                         const unsigned b[2]) {
    asm volatile(
        "mma.sync.aligned.m16n8k16.row.col.f32.bf16.bf16.f32 "
        "{%0,%1,%2,%3}, {%4,%5,%6,%7}, {%8,%9}, {%0,%1,%2,%3};"
        : "+f"(c[0]), "+f"(c[1]), "+f"(c[2]), "+f"(c[3])
        : "r"(a[0]), "r"(a[1]), "r"(a[2]), "r"(a[3]), "r"(b[0]), "r"(b[1]));
}

// ---------------- CSR build --------------------------------------------------
__global__ void k_hist(const int* __restrict__ dst, int E, int* __restrict__ deg) {
    int i = blockIdx.x * blockDim.x + threadIdx.x;
    if (i < E) atomicAdd(&deg[dst[i]], 1);
}

__global__ void k_scan(int* __restrict__ deg_cursor, int* __restrict__ rowptr, int N, int E) {
    __shared__ int part[1024];
    int tid = threadIdx.x;
    int chunk = (N + 1023) >> 10;
    int beg = tid * chunk;
    int end = min(beg + chunk, N);
    int s = 0;
    for (int i = beg; i < end; i++) s += deg_cursor[i];
    part[tid] = s;
    __syncthreads();
    for (int off = 1; off < 1024; off <<= 1) {
        int v = (tid >= off) ? part[tid - off] : 0;
        __syncthreads();
        part[tid] += v;
        __syncthreads();
    }
    int run = (tid > 0) ? part[tid - 1] : 0;
    for (int i = beg; i < end; i++) {
        int d = deg_cursor[i];
        rowptr[i] = run;
        deg_cursor[i] = run;
        run += d;
    }
    if (tid == 0) rowptr[N] = E;
}

__global__ void k_scatter(const int* __restrict__ src, const int* __restrict__ dst,
                          int E, int* __restrict__ cursor, int* __restrict__ csrc) {
    int i = blockIdx.x * blockDim.x + threadIdx.x;
    if (i < E) {
        int p = atomicAdd(&cursor[dst[i]], 1);
        csrc[p] = src[i];
    }
}

// ---------------- bf16 tensor-core GEMM: H[M,128] = X[M,128] @ W[128,128] ----
// 128x128 block tile, 8 warps (32x64 warp tile), m16n8k16, fragment-packed smem.
// Packed layout: word addr = row*PITCH + chunk*8 + tig*2 holds
//   uint2{ bf16x2(k0,k0+1), bf16x2(k0+8,k0+9) } with k0 = chunk*16 + tig*2.
__global__ void __launch_bounds__(256) k_gemm_tc(
    const float* __restrict__ X, const float* __restrict__ W,
    float* __restrict__ H, int M) {
    extern __shared__ unsigned smu[];
    unsigned* Ws = smu;                 // [n][PITCH] packed (W transposed)
    unsigned* Xs = smu + 128 * PITCH;   // [row][PITCH] packed
    int tid = threadIdx.x;
    int m0 = blockIdx.x * 128;
    int rows = min(128, M - m0);

    // stage W transposed + packed (coalesced global reads along n)
    for (int i = tid; i < 128 * 32; i += 256) {
        int n = i & 127, ct = i >> 7;
        int c = ct >> 2, t = ct & 3;
        int k0 = c * 16 + t * 2;
        float w0 = W[k0 * 128 + n],       w1 = W[(k0 + 1) * 128 + n];
        float w2 = W[(k0 + 8) * 128 + n], w3 = W[(k0 + 9) * 128 + n];
        *(uint2*)(Ws + n * PITCH + c * 8 + t * 2) =
            make_uint2(packbf(w0, w1), packbf(w2, w3));
    }
    // stage X packed
    for (int i = tid; i < 128 * 32; i += 256) {
        int r = i >> 5, ct = i & 31;
        int c = ct >> 2, t = ct & 3;
        int k0 = c * 16 + t * 2;
        float2 lo = make_float2(0.f, 0.f), hi = lo;
        if (r < rows) {
            const float* row = X + (size_t)(m0 + r) * 128;
            lo = *(const float2*)(row + k0);
            hi = *(const float2*)(row + k0 + 8);
        }
        *(uint2*)(Xs + r * PITCH + c * 8 + t * 2) =
            make_uint2(packbf(lo.x, lo.y), packbf(hi.x, hi.y));
    }
    __syncthreads();

    int wid = tid >> 5, lane = tid & 31;
    int rg = wid & 3, cg = wid >> 2;
    int r0 = rg * 32, n0 = cg * 64;
    int gid = lane >> 2, tig = lane & 3;

    float acc[2][8][4];
#pragma unroll
    for (int mi = 0; mi < 2; mi++)
#pragma unroll
        for (int ni = 0; ni < 8; ni++)
#pragma unroll
            for (int j = 0; j < 4; j++) acc[mi][ni][j] = 0.f;

#pragma unroll
    for (int kk = 0; kk < 8; kk++) {
        int ko = kk * 8 + tig * 2;
        unsigned a[2][4], b[8][2];
#pragma unroll
        for (int mi = 0; mi < 2; mi++) {
            uint2 u0 = *(uint2*)(Xs + (r0 + mi * 16 + gid) * PITCH + ko);
            uint2 u1 = *(uint2*)(Xs + (r0 + mi * 16 + 8 + gid) * PITCH + ko);
            a[mi][0] = u0.x; a[mi][1] = u1.x; a[mi][2] = u0.y; a[mi][3] = u1.y;
        }
#pragma unroll
        for (int ni = 0; ni < 8; ni++) {
            uint2 v = *(uint2*)(Ws + (n0 + ni * 8 + gid) * PITCH + ko);
            b[ni][0] = v.x; b[ni][1] = v.y;
        }
#pragma unroll
        for (int mi = 0; mi < 2; mi++)
#pragma unroll
            for (int ni = 0; ni < 8; ni++) mma_bf16(acc[mi][ni], a[mi], b[ni]);
    }

#pragma unroll
    for (int mi = 0; mi < 2; mi++) {
        int rlo = r0 + mi * 16 + gid;
#pragma unroll
        for (int ni = 0; ni < 8; ni++) {
            int col = n0 + ni * 8 + tig * 2;
            if (rlo < rows)
                *(float2*)(H + (size_t)(m0 + rlo) * 128 + col) =
                    make_float2(acc[mi][ni][0], acc[mi][ni][1]);
            if (rlo + 8 < rows)
                *(float2*)(H + (size_t)(m0 + rlo + 8) * 128 + col) =
                    make_float2(acc[mi][ni][2], acc[mi][ni][3]);
        }
    }
}

// ---------------- per-node attention scores ----------------------------------
__global__ void k_scores(const float* __restrict__ h, const float* __restrict__ asrc,
                         const float* __restrict__ adst, float* __restrict__ ss,
                         float* __restrict__ sd, int N) {
    int gt = blockIdx.x * blockDim.x + threadIdx.x;
    int w = gt >> 5, lane = gt & 31;
    if (w >= N) return;
    float4 hv = *(const float4*)(h + (size_t)w * 128 + lane * 4);
    float4 a1 = ((const float4*)asrc)[lane];
    float4 a2 = ((const float4*)adst)[lane];
    float d1 = hv.x * a1.x + hv.y * a1.y + hv.z * a1.z + hv.w * a1.w;
    float d2 = hv.x * a2.x + hv.y * a2.y + hv.z * a2.z + hv.w * a2.w;
#pragma unroll
    for (int o = 16; o; o >>= 1) {
        d1 += __shfl_xor_sync(0xffffffffu, d1, o);
        d2 += __shfl_xor_sync(0xffffffffu, d2, o);
    }
    if (lane == 0) { ss[w] = d1; sd[w] = d2; }
}

// ---------------- warp-per-dst softmax-weighted aggregation ------------------
__global__ void k_agg(const float* __restrict__ h, const float* __restrict__ ss,
                      const float* __restrict__ sdv, const int* __restrict__ rowptr,
                      const int* __restrict__ csrc, float* __restrict__ out, int N) {
    int gt = blockIdx.x * blockDim.x + threadIdx.x;
    int w = gt >> 5, lane = gt & 31;
    if (w >= N) return;
    int beg = rowptr[w], end = rowptr[w + 1];
    float sd = sdv[w];

    float mx = -1e30f;
    for (int k = beg + lane; k < end; k += 32) {
        float e = ss[csrc[k]] + sd;
        e = (e > 0.f) ? e : 0.2f * e;
        mx = fmaxf(mx, e);
    }
#pragma unroll
    for (int o = 16; o; o >>= 1) mx = fmaxf(mx, __shfl_xor_sync(0xffffffffu, mx, o));

    float4 acc = make_float4(0.f, 0.f, 0.f, 0.f);
    float den = 0.f;
    for (int k = beg; k < end; k++) {
        int s = csrc[k];
        float e = ss[s] + sd;
        e = (e > 0.f) ? e : 0.2f * e;
        float wgt = __expf(e - mx);
        den += wgt;
        float4 hv = *(const float4*)(h + (size_t)s * 128 + lane * 4);
        acc.x = fmaf(wgt, hv.x, acc.x);
        acc.y = fmaf(wgt, hv.y, acc.y);
        acc.z = fmaf(wgt, hv.z, acc.z);
        acc.w = fmaf(wgt, hv.w, acc.w);
    }
    float inv = 1.f / (den + 1e-16f);
    *(float4*)(out + (size_t)w * 128 + lane * 4) =
        make_float4(acc.x * inv, acc.y * inv, acc.z * inv, acc.w * inv);
}

// ---------------- bias + BN(eval) + ReLU, in-place ---------------------------
__global__ void k_bnrelu(float* __restrict__ x, const float* __restrict__ b,
                         const float* __restrict__ gamma, const float* __restrict__ beta,
                         const float* __restrict__ rmean, const float* __restrict__ rvar,
                         int N) {
    int idx = blockIdx.x * blockDim.x + threadIdx.x;
    if (idx >= N * 32) return;
    int c4 = idx & 31;
    float4 xv = ((float4*)x)[idx];
    float4 bb = ((const float4*)b)[c4];
    float4 gg = ((const float4*)gamma)[c4];
    float4 bt = ((const float4*)beta)[c4];
    float4 mm = ((const float4*)rmean)[c4];
    float4 vv = ((const float4*)rvar)[c4];
    float4 o;
    o.x = fmaxf((xv.x + bb.x - mm.x) * rsqrtf(vv.x + 1e-5f) * gg.x + bt.x, 0.f);
    o.y = fmaxf((xv.y + bb.y - mm.y) * rsqrtf(vv.y + 1e-5f) * gg.y + bt.y, 0.f);
    o.z = fmaxf((xv.z + bb.z - mm.z) * rsqrtf(vv.z + 1e-5f) * gg.z + bt.z, 0.f);
    o.w = fmaxf((xv.w + bb.w - mm.w) * rsqrtf(vv.w + 1e-5f) * gg.w + bt.w, 0.f);
    ((float4*)x)[idx] = o;
}

// ---------------- fused link predictor (bf16 tensor core) --------------------
__global__ void __launch_bounds__(256) k_pred_tc(
    const float* __restrict__ x, const float* __restrict__ b2,
    const float* __restrict__ Wp1, const float* __restrict__ bp1,
    const float* __restrict__ Wp2, const float* __restrict__ bp2,
    const int* __restrict__ edges, int Q, float* __restrict__ out) {
    extern __shared__ unsigned smu[];
    unsigned* Ws = smu;                         // [n][PITCH] packed (Wp1 transposed)
    unsigned* Hs = smu + 128 * PITCH;           // [q][PITCH] packed gathered products
    float* bp1s = (float*)(smu + 2 * 128 * PITCH);  // 128
    float* wp2s = bp1s + 128;                       // 128
    float* b2s  = wp2s + 128;                       // 128
    float* red  = b2s + 128;                        // [128][8]
    int tid = threadIdx.x;
    int q0 = blockIdx.x * 128;

    for (int i = tid; i < 128 * 32; i += 256) {
        int n = i & 127, ct = i >> 7;
        int c = ct >> 2, t = ct & 3;
        int k0 = c * 16 + t * 2;
        float w0 = Wp1[k0 * 128 + n],       w1 = Wp1[(k0 + 1) * 128 + n];
        float w2 = Wp1[(k0 + 8) * 128 + n], w3 = Wp1[(k0 + 9) * 128 + n];
        *(uint2*)(Ws + n * PITCH + c * 8 + t * 2) =
            make_uint2(packbf(w0, w1), packbf(w2, w3));
    }
    if (tid < 128) { bp1s[tid] = bp1[tid]; wp2s[tid] = Wp2[tid]; b2s[tid] = b2[tid]; }
    __syncthreads();   // b2s ready before gather

    for (int i = tid; i < 128 * 32; i += 256) {
        int r = i >> 5, ct = i & 31;
        int c = ct >> 2, t = ct & 3;
        int k0 = c * 16 + t * 2;
        int q = q0 + r;
        float p0 = 0.f, p1 = 0.f, p2 = 0.f, p3 = 0.f;
        if (q < Q) {
            int e0 = edges[q], e1 = edges[Q + q];
            const float* xa = x + (size_t)e0 * 128;
            const float* xb = x + (size_t)e1 * 128;
            float2 alo = *(const float2*)(xa + k0), ahi = *(const float2*)(xa + k0 + 8);
            float2 blo = *(const float2*)(xb + k0), bhi = *(const float2*)(xb + k0 + 8);
            float2 clo = *(const float2*)(b2s + k0), chi = *(const float2*)(b2s + k0 + 8);
            p0 = (alo.x + clo.x) * (blo.x + clo.x);
            p1 = (alo.y + clo.y) * (blo.y + clo.y);
            p2 = (ahi.x + chi.x) * (bhi.x + chi.x);
            p3 = (ahi.y + chi.y) * (bhi.y + chi.y);
        }
        *(uint2*)(Hs + r * PITCH + c * 8 + t * 2) =
            make_uint2(packbf(p0, p1), packbf(p2, p3));
    }
    __syncthreads();

    int wid = tid >> 5, lane = tid & 31;
    int rg = wid & 3, cg = wid >> 2;
    int r0 = rg * 32, n0 = cg * 64;
    int gid = lane >> 2, tig = lane & 3;

    float acc[2][8][4];
#pragma unroll
    for (int mi = 0; mi < 2; mi++)
#pragma unroll
        for (int ni = 0; ni < 8; ni++)
#pragma unroll
            for (int j = 0; j < 4; j++) acc[mi][ni][j] = 0.f;

#pragma unroll
    for (int kk = 0; kk < 8; kk++) {
        int ko = kk * 8 + tig * 2;
        unsigned a[2][4], b[8][2];
#pragma unroll
        for (int mi = 0; mi < 2; mi++) {
            uint2 u0 = *(uint2*)(Hs + (r0 + mi * 16 + gid) * PITCH + ko);
            uint2 u1 = *(uint2*)(Hs + (r0 + mi * 16 + 8 + gid) * PITCH + ko);
            a[mi][0] = u0.x; a[mi][1] = u1.x; a[mi][2] = u0.y; a[mi][3] = u1.y;
        }
#pragma unroll
        for (int ni = 0; ni < 8; ni++) {
            uint2 v = *(uint2*)(Ws + (n0 + ni * 8 + gid) * PITCH + ko);
            b[ni][0] = v.x; b[ni][1] = v.y;
        }
#pragma unroll
        for (int mi = 0; mi < 2; mi++)
#pragma unroll
            for (int ni = 0; ni < 8; ni++) mma_bf16(acc[mi][ni], a[mi], b[ni]);
    }

    // epilogue: relu(acc + bp1) dot wp2, partial per thread, reduce via smem
    int slot = cg * 4 + tig;
#pragma unroll
    for (int mi = 0; mi < 2; mi++) {
        float plo = 0.f, phi = 0.f;
#pragma unroll
        for (int ni = 0; ni < 8; ni++) {
            int col = n0 + ni * 8 + tig * 2;
            float w0 = wp2s[col], w1 = wp2s[col + 1];
            float bb0 = bp1s[col], bb1 = bp1s[col + 1];
            plo += fmaxf(acc[mi][ni][0] + bb0, 0.f) * w0
                 + fmaxf(acc[mi][ni][1] + bb1, 0.f) * w1;
            phi += fmaxf(acc[mi][ni][2] + bb0, 0.f) * w0
                 + fmaxf(acc[mi][ni][3] + bb1, 0.f) * w1;
        }
        int rlo = r0 + mi * 16 + gid;
        red[rlo * 8 + slot] = plo;
        red[(rlo + 8) * 8 + slot] = phi;
    }
    __syncthreads();

    if (tid < 128) {
        float s = 0.f;
#pragma unroll
        for (int j = 0; j < 8; j++) s += red[tid * 8 + j];
        int q = q0 + tid;
        if (q < Q) out[q] = 1.f / (1.f + __expf(-(s + bp2[0])));
    }
}

// ---------------- launch ------------------------------------------------------
extern "C" void kernel_launch(void* const* d_in, const int* in_sizes, int n_in,
                              void* d_out, int out_size) {
    const float* emb    = (const float*)d_in[0];
    const float* W1     = (const float*)d_in[1];
    const float* a_src1 = (const float*)d_in[2];
    const float* a_dst1 = (const float*)d_in[3];
    const float* b1     = (const float*)d_in[4];
    const float* gamma  = (const float*)d_in[5];
    const float* beta   = (const float*)d_in[6];
    const float* rmean  = (const float*)d_in[7];
    const float* rvar   = (const float*)d_in[8];
    const float* W2     = (const float*)d_in[9];
    const float* a_src2 = (const float*)d_in[10];
    const float* a_dst2 = (const float*)d_in[11];
    const float* b2     = (const float*)d_in[12];
    const float* Wp1    = (const float*)d_in[13];
    const float* bp1    = (const float*)d_in[14];
    const float* Wp2    = (const float*)d_in[15];
    const float* bp2    = (const float*)d_in[16];
    const int*   eidx   = (const int*)d_in[17];
    const int*   edges  = (const int*)d_in[18];

    int N = in_sizes[0] / C_DIM;
    int E = in_sizes[17] / 2;
    int Q = in_sizes[18] / 2;

    float *h, *agg, *ss, *sd;
    int *rowptr, *cursor, *csrc;
    cudaGetSymbolAddress((void**)&h, g_h);
    cudaGetSymbolAddress((void**)&agg, g_agg);
    cudaGetSymbolAddress((void**)&ss, g_ss);
    cudaGetSymbolAddress((void**)&sd, g_sd);
    cudaGetSymbolAddress((void**)&rowptr, g_rowptr);
    cudaGetSymbolAddress((void**)&cursor, g_cursor);
    cudaGetSymbolAddress((void**)&csrc, g_csrc);

    const size_t smg = (size_t)2 * 128 * PITCH * 4;                 // 73728
    const size_t smp = smg + (size_t)(3 * 128 + 128 * 8) * 4;       // +5632
    cudaFuncSetAttribute(k_gemm_tc, cudaFuncAttributeMaxDynamicSharedMemorySize, (int)smg);
    cudaFuncSetAttribute(k_pred_tc, cudaFuncAttributeMaxDynamicSharedMemorySize, (int)smp);

    const int TB = 256;
    const int nw_blocks = (N * 32 + TB - 1) / TB;

    // CSR by destination (shared by both convs)
    cudaMemsetAsync(cursor, 0, N * sizeof(int));
    k_hist<<<(E + TB - 1) / TB, TB>>>(eidx + E, E, cursor);
    k_scan<<<1, 1024>>>(cursor, rowptr, N, E);
    k_scatter<<<(E + TB - 1) / TB, TB>>>(eidx, eidx + E, E, cursor, csrc);

    // conv1
    k_gemm_tc<<<(N + 127) / 128, 256, smg>>>(emb, W1, h, N);
    k_scores<<<nw_blocks, TB>>>(h, a_src1, a_dst1, ss, sd, N);
    k_agg<<<nw_blocks, TB>>>(h, ss, sd, rowptr, csrc, agg, N);
    k_bnrelu<<<nw_blocks, TB>>>(agg, b1, gamma, beta, rmean, rvar, N);

    // conv2
    k_gemm_tc<<<(N + 127) / 128, 256, smg>>>(agg, W2, h, N);
    k_scores<<<nw_blocks, TB>>>(h, a_src2, a_dst2, ss, sd, N);
    k_agg<<<nw_blocks, TB>>>(h, ss, sd, rowptr, csrc, agg, N);

    // link predictor
    k_pred_tc<<<(Q + 127) / 128, 256, smp>>>(agg, b2, Wp1, bp1, Wp2, bp2, edges, Q,
                                             (float*)d_out);
}